// round 4
// baseline (speedup 1.0000x reference)
#include <cuda_runtime.h>

#define NGROUPS 512   // B*S/16
#define NSLOTS  64    // E*Sets
#define DDIM    512
#define TTOK    16
#define FDIM    32

typedef unsigned long long ull;
union U2 { ull u; float2 f; };

// packed fp32x2 FMA (sm_100+): d.lo += a.lo*b.lo ; d.hi += a.hi*b.hi
__device__ __forceinline__ void ffma2(ull& d, ull a, ull b) {
    asm("fma.rn.f32x2 %0, %1, %2, %0;" : "+l"(d) : "l"(a), "l"(b));
}
__device__ __forceinline__ ull bcast2(float x) {
    ull r; asm("mov.b64 %0, {%1, %1};" : "=l"(r) : "f"(x)); return r;
}
__device__ __forceinline__ ull pack2(float lo, float hi) {
    ull r; asm("mov.b64 %0, {%1, %2};" : "=l"(r) : "f"(lo), "f"(hi)); return r;
}

__device__ int g_winners[NGROUPS * NSLOTS];

// ---------------------------------------------------------------------------
// Kernel 1: routing (unchanged from R3 — ~2us, exact argmax w/ coop fp64
// recheck of near-ties).
// ---------------------------------------------------------------------------
__global__ __launch_bounds__(256) void k_route(const float* __restrict__ x,
                                               const float* __restrict__ ctrl,
                                               float* __restrict__ out)
{
    extern __shared__ float sm[];
    float* xs   = sm;                        // 16 x 512 tokens (32 KB)
    float* part = sm + 8192;                 // 256 x 16 partials (16 KB)
    float* ls   = sm + 12288;                // 64 x 16 logits (4 KB)
    double* dred = (double*)(sm + 13312);    // 256 doubles (2 KB)
    __shared__ int sflags[64];
    __shared__ int swin[64];
    __shared__ int snf;
    __shared__ double dlog[16];

    const int G   = blockIdx.x;
    const int tid = threadIdx.x;

    if (tid == 0) snf = 0;

    const float4* src = (const float4*)(x + (size_t)G * 8192);
    float4* dst = (float4*)(out + (size_t)G * 8192);
    float4* xs4 = (float4*)xs;
    const float4 z4 = make_float4(0.f, 0.f, 0.f, 0.f);
    for (int i = tid; i < 2048; i += 256) { xs4[i] = src[i]; dst[i] = z4; }
    __syncthreads();

    {
        const int sq = tid & 15;
        const int tq = (tid >> 4) & 3;
        const int ks = tid >> 6;
        const int kbase = ks * 128;

        U2 acc[4][2];
        #pragma unroll
        for (int t = 0; t < 4; ++t) { acc[t][0].u = 0ull; acc[t][1].u = 0ull; }

        const float* cbase = ctrl + sq * 4;
        const float* x0 = xs + tq * 4 * DDIM;

        for (int kk = 0; kk < 128; kk += 4) {
            const int k = kbase + kk;
            ulonglong2 w[4];
            #pragma unroll
            for (int j = 0; j < 4; ++j)
                w[j] = __ldg((const ulonglong2*)(cbase + (size_t)(k + j) * 64));
            float xv[4][4];
            #pragma unroll
            for (int t = 0; t < 4; ++t)
                *(float4*)&xv[t][0] = *(const float4*)(x0 + t * DDIM + k);
            #pragma unroll
            for (int j = 0; j < 4; ++j) {
                #pragma unroll
                for (int t = 0; t < 4; ++t) {
                    ull xb = bcast2(xv[t][j]);
                    ffma2(acc[t][0].u, xb, w[j].x);
                    ffma2(acc[t][1].u, xb, w[j].y);
                }
            }
        }
        #pragma unroll
        for (int t = 0; t < 4; ++t) {
            part[tid * 16 + t * 4 + 0] = acc[t][0].f.x;
            part[tid * 16 + t * 4 + 1] = acc[t][0].f.y;
            part[tid * 16 + t * 4 + 2] = acc[t][1].f.x;
            part[tid * 16 + t * 4 + 3] = acc[t][1].f.y;
        }
    }
    __syncthreads();

    {
        const int s   = tid & 63;
        const int tq2 = tid >> 6;
        const int sq2 = s >> 2, sl = s & 3;
        const float step = 1e-6f / 15.f;
        #pragma unroll
        for (int tl = 0; tl < 4; ++tl) {
            float v = 0.f;
            #pragma unroll
            for (int c = 0; c < 4; ++c)
                v += part[(c * 64 + tq2 * 16 + sq2) * 16 + tl * 4 + sl];
            const int t = tq2 * 4 + tl;
            ls[s * 16 + t] = v + step * (float)t;
        }
    }
    __syncthreads();

    if (tid < 64) {
        const int s = tid;
        float best = -3.4e38f, second = -3.4e38f;
        int bi = 0;
        #pragma unroll
        for (int t = 0; t < TTOK; ++t) {
            float v = ls[s * 16 + t];
            if (v >= best) { second = best; best = v; bi = t; }
            else if (v > second) { second = v; }
        }
        swin[s] = bi;
        if (best - second < 2e-5f) {
            int p = atomicAdd(&snf, 1);
            sflags[p] = s;
        }
    }
    __syncthreads();

    const int nf = snf;
    for (int i = 0; i < nf; ++i) {
        const int s = sflags[i];
        const int t = tid >> 4, j = tid & 15;
        double a = 0.0;
        const float* xr = xs + t * DDIM + j * 32;
        const float* cp = ctrl + (size_t)(j * 32) * 64 + s;
        #pragma unroll 8
        for (int k = 0; k < 32; ++k)
            a += (double)xr[k] * (double)__ldg(cp + (size_t)k * 64);
        dred[t * 16 + j] = a;
        __syncthreads();
        if (tid < 16) {
            double tot = 0.0;
            #pragma unroll
            for (int j2 = 0; j2 < 16; ++j2) tot += dred[tid * 16 + j2];
            dlog[tid] = tot + (double)tid * (1e-6 / 15.0);
        }
        __syncthreads();
        if (tid == 0) {
            double best = -1e300; int bi = 0;
            #pragma unroll
            for (int t2 = 0; t2 < TTOK; ++t2)
                if (dlog[t2] >= best) { best = dlog[t2]; bi = t2; }
            swin[s] = bi;
        }
        __syncthreads();
    }

    if (tid < 64) g_winners[G * 64 + tid] = swin[tid];
}

// ---------------------------------------------------------------------------
// Kernel 2: per-slot expert FFN. Grid (16 group-chunks, 64 slots), 32 rows/CTA.
// GEMM1: warp = (8-row set, 256-k half), lane = f. All Xg reads are warp-
// uniform broadcast LDS.128 (zero conflicts); f1 reads lane-coalesced LDG.32;
// FFMA2 pairs along k (acc.lo/hi = even/odd-k partials).
// ---------------------------------------------------------------------------
__global__ __launch_bounds__(256, 2) void k_expert(const float* __restrict__ x,
                                                   const float* __restrict__ f1,
                                                   const float* __restrict__ f2,
                                                   float* __restrict__ out)
{
    extern __shared__ float sm[];
    float* Xg   = sm;                    // 32 x 512 (64 KB)
    float* part = sm + 16384;            // 8 warps x 32 f x 8 r (8 KB)
    float* YT   = sm + 16384 + 2048;     // 32 f x 36 (4.5 KB)
    __shared__ int rowb[32];

    const int slot = blockIdx.y;
    const int g0   = blockIdx.x * 32;
    const int tid  = threadIdx.x;

    if (tid < 32) {
        int w = g_winners[(g0 + tid) * 64 + slot];
        rowb[tid] = ((g0 + tid) * TTOK + w) * DDIM;
    }
    __syncthreads();

    for (int i = tid; i < 32 * 128; i += 256) {
        int r = i >> 7, k4 = i & 127;
        *(float4*)(Xg + r * DDIM + k4 * 4) = __ldg((const float4*)(x + rowb[r]) + k4);
    }
    __syncthreads();

    // ---- GEMM1: conflict-free broadcast formulation
    {
        const int wid  = tid >> 5;       // 0..7
        const int lane = tid & 31;       // f
        const int rset = wid & 3;        // 8 rows each
        const int kh   = wid >> 2;       // k half (256)
        const int k0   = kh * 256;

        U2 acc[8];
        #pragma unroll
        for (int r = 0; r < 8; ++r) acc[r].u = 0ull;

        const float* wp = f1 + slot * 32 + lane;
        const float* xr = Xg + rset * 8 * DDIM;

        #pragma unroll 2
        for (int i = 0; i < 256; i += 4) {
            const int k = k0 + i;
            float w0 = __ldg(wp + (size_t)(k + 0) * 2048);
            float w1 = __ldg(wp + (size_t)(k + 1) * 2048);
            float w2 = __ldg(wp + (size_t)(k + 2) * 2048);
            float w3 = __ldg(wp + (size_t)(k + 3) * 2048);
            const ull p01 = pack2(w0, w1);
            const ull p23 = pack2(w2, w3);
            #pragma unroll
            for (int r = 0; r < 8; ++r) {
                const ulonglong2 xq = *(const ulonglong2*)(xr + r * DDIM + k);
                ffma2(acc[r].u, xq.x, p01);   // k, k+1
                ffma2(acc[r].u, xq.y, p23);   // k+2, k+3
            }
        }
        float* pp = part + ((size_t)wid * 32 + lane) * 8;
        #pragma unroll
        for (int r = 0; r < 8; ++r) pp[r] = acc[r].f.x + acc[r].f.y;
    }
    __syncthreads();

    // reduce k-halves + relu -> YT[f*36 + r]
    {
        const int f  = tid >> 3;
        const int rl = tid & 7;
        #pragma unroll
        for (int j = 0; j < 4; ++j) {
            float v = part[((size_t)(j)     * 32 + f) * 8 + rl]
                    + part[((size_t)(4 + j) * 32 + f) * 8 + rl];
            YT[f * 36 + j * 8 + rl] = fmaxf(v, 0.f);
        }
    }
    __syncthreads();

    // ---- GEMM2: warp owns 64-wide d chunk, lane owns 2 d; acc over row-pairs
    {
        const int lane = tid & 31;
        const int wq   = tid >> 5;
        const int d0   = wq * 64 + lane * 2;

        U2 acc[16][2];
        #pragma unroll
        for (int p = 0; p < 16; ++p) { acc[p][0].u = 0ull; acc[p][1].u = 0ull; }

        const float* w2p = f2 + slot * (FDIM * DDIM) + d0;
        #pragma unroll 4
        for (int k = 0; k < FDIM; ++k) {
            const float2 wv = __ldg((const float2*)(w2p + k * DDIM));
            const ull wb0 = bcast2(wv.x);
            const ull wb1 = bcast2(wv.y);
            const ulonglong2* yp = (const ulonglong2*)(YT + k * 36);
            #pragma unroll
            for (int q = 0; q < 8; ++q) {
                const ulonglong2 y = yp[q];     // rows (4q,4q+1),(4q+2,4q+3)
                ffma2(acc[2*q  ][0].u, y.x, wb0);
                ffma2(acc[2*q  ][1].u, y.x, wb1);
                ffma2(acc[2*q+1][0].u, y.y, wb0);
                ffma2(acc[2*q+1][1].u, y.y, wb1);
            }
        }
        #pragma unroll
        for (int p = 0; p < 16; ++p) {
            atomicAdd((float2*)(out + rowb[2*p    ] + d0),
                      make_float2(acc[p][0].f.x, acc[p][1].f.x));
            atomicAdd((float2*)(out + rowb[2*p + 1] + d0),
                      make_float2(acc[p][0].f.y, acc[p][1].f.y));
        }
    }
}

// ---------------------------------------------------------------------------
extern "C" void kernel_launch(void* const* d_in, const int* in_sizes, int n_in,
                              void* d_out, int out_size)
{
    (void)in_sizes; (void)n_in; (void)out_size;
    const float* x    = (const float*)d_in[0];
    const float* ctrl = (const float*)d_in[1];
    const float* f1   = (const float*)d_in[2];
    const float* f2   = (const float*)d_in[3];
    float* out = (float*)d_out;

    const int smem1 = 13312 * 4 + 2048;                            // 55296
    const int smem2 = (16384 + 2048 + 1152) * (int)sizeof(float);  // 78336
    cudaFuncSetAttribute(k_route,  cudaFuncAttributeMaxDynamicSharedMemorySize, smem1);
    cudaFuncSetAttribute(k_expert, cudaFuncAttributeMaxDynamicSharedMemorySize, smem2);

    k_route<<<NGROUPS, 256, smem1>>>(x, ctrl, out);
    k_expert<<<dim3(16, 64), 256, smem2>>>(x, f1, f2, out);
}